// round 1
// baseline (speedup 1.0000x reference)
#include <cuda_runtime.h>
#include <math.h>

// ---------------------------------------------------------------------------
// SimpleNet quanvolutional pipeline, sm_103a
//   x (1,1,512,512) -> qconv(4ch, 511x511) -> sigmoid -> pool2 -> (4,255,255)
//   -> conv2 5x5 (20ch) relu pool2 -> (20,125,125)
//   -> conv3 3x3 (40ch) relu -> (40,123,123) -> adaptive max 4x4 -> 640
//   -> fc1(64) relu -> fc2(10)
//
// Quantum sim reduced to: ez[w] = r^T A_w r, with r_i the real product vector
// from the RX encoding and A_w a fixed real-symmetric 16x16 matrix computed
// from q_weights once per launch.
// ---------------------------------------------------------------------------

__device__ float g_A[1024];          // 4 x 16 x 16
__device__ float g_h1[4 * 255 * 255];
__device__ float g_h2[20 * 125 * 125];
__device__ float g_bins[640];        // adaptive-max bins (atomicMax as int)

// ---------------------------------------------------------------------------
// k_prep: simulate the weight circuit on all 16 basis columns -> U, then
// A_w[i,j] = Re( (-i)^(popc(j)-popc(i)) * sum_k z_w(k) conj(U[k,i]) U[k,j] ).
// Also zeroes the adaptive-max bins for this launch.
// ---------------------------------------------------------------------------
__global__ void k_prep(const float* __restrict__ qw) {
    int t = threadIdx.x;                 // 0..255
    for (int b = t; b < 640; b += 256) ((int*)g_bins)[b] = 0;

    __shared__ float Ur[16][16], Ui[16][16];

    if (t < 16) {
        int k = t;
        float pr[16], pi[16];
        #pragma unroll
        for (int i = 0; i < 16; i++) { pr[i] = (i == k) ? 1.f : 0.f; pi[i] = 0.f; }

        for (int l = 0; l < 3; l++) {
            for (int w = 0; w < 4; w++) {
                float phi = qw[(l * 4 + w) * 3 + 0];
                float th  = qw[(l * 4 + w) * 3 + 1];
                float om  = qw[(l * 4 + w) * 3 + 2];
                float st, ct, sap, cap, sam, cam;
                sincosf(0.5f * th, &st, &ct);
                sincosf(0.5f * (phi + om), &sap, &cap);
                sincosf(0.5f * (phi - om), &sam, &cam);
                float u00r =  cap * ct, u00i = -sap * ct;
                float u01r = -cam * st, u01i = -sam * st;
                float u10r =  cam * st, u10i = -sam * st;
                float u11r =  cap * ct, u11i =  sap * ct;
                int m = 8 >> w;
                for (int i0 = 0; i0 < 16; i0++) {
                    if (i0 & m) continue;
                    int i1 = i0 | m;
                    float a0r = pr[i0], a0i = pi[i0];
                    float a1r = pr[i1], a1i = pi[i1];
                    pr[i0] = u00r * a0r - u00i * a0i + u01r * a1r - u01i * a1i;
                    pi[i0] = u00r * a0i + u00i * a0r + u01r * a1i + u01i * a1r;
                    pr[i1] = u10r * a0r - u10i * a0i + u11r * a1r - u11i * a1i;
                    pi[i1] = u10r * a0i + u10i * a0r + u11r * a1i + u11i * a1r;
                }
            }
            int r = l % 3 + 1;
            for (int w = 0; w < 4; w++) {
                int cm = 8 >> w;
                int tm = 8 >> ((w + r) & 3);
                for (int i = 0; i < 16; i++) {
                    if ((i & cm) && !(i & tm)) {
                        int j = i | tm;
                        float tr = pr[i], ti = pi[i];
                        pr[i] = pr[j]; pi[i] = pi[j];
                        pr[j] = tr;    pi[j] = ti;
                    }
                }
            }
        }
        #pragma unroll
        for (int i = 0; i < 16; i++) { Ur[i][k] = pr[i]; Ui[i][k] = pi[i]; }
    }
    __syncthreads();

    for (int e = t; e < 1024; e += 256) {
        int w = e >> 8, i = (e >> 4) & 15, j = e & 15;
        float mr = 0.f, mi = 0.f;
        #pragma unroll
        for (int kk = 0; kk < 16; kk++) {
            float z  = ((kk >> (3 - w)) & 1) ? -1.f : 1.f;
            float ar = Ur[kk][i], ai = Ui[kk][i];
            float br = Ur[kk][j], bi = Ui[kk][j];
            mr += z * (ar * br + ai * bi);
            mi += z * (ar * bi - ai * br);
        }
        int d = (__popc(j) - __popc(i)) & 3;
        float A = (d == 0) ? mr : (d == 1) ? mi : (d == 2) ? -mr : -mi;
        g_A[e] = A;
    }
}

// ---------------------------------------------------------------------------
// k_qconv: per pooled pixel (py,px) compute 4 patches' ez[4], pool (max),
// sigmoid, store to g_h1[4][255][255].
// ---------------------------------------------------------------------------
__global__ void __launch_bounds__(128) k_qconv(const float* __restrict__ img) {
    __shared__ float4 As[256];           // 4 * 16 rows * 4 float4
    {
        int tid = threadIdx.y * 16 + threadIdx.x;
        for (int q = tid; q < 256; q += 128) As[q] = ((const float4*)g_A)[q];
    }
    __syncthreads();

    int px = blockIdx.x * 16 + threadIdx.x;
    int py = blockIdx.y * 8 + threadIdx.y;
    if (px >= 255 || py >= 255) return;

    // cos/sin of half-angles for the 3x3 pixel block feeding the 4 patches
    float cc[9], ss[9];
    int y0 = 2 * py, x0 = 2 * px;
    #pragma unroll
    for (int d = 0; d < 9; d++) {
        int dy = d / 3, dx = d % 3;
        float v = 0.5f * img[(y0 + dy) * 512 + (x0 + dx)];
        sincosf(v, &ss[d], &cc[d]);
    }

    // r vectors for the 4 patches: r_i = prod over qubits (bit? s : c)
    float r[4][16];
    #pragma unroll
    for (int p = 0; p < 4; p++) {
        int dy = p >> 1, dx = p & 1;
        int ia = dy * 3 + dx, ib = ia + 1, ic = ia + 3, id = ia + 4;
        float c0 = cc[ia], s0 = ss[ia], c1 = cc[ib], s1 = ss[ib];
        float c2 = cc[ic], s2 = ss[ic], c3 = cc[id], s3 = ss[id];
        float hi[4] = { c0 * c1, c0 * s1, s0 * c1, s0 * s1 };
        float lo[4] = { c2 * c3, c2 * s3, s2 * c3, s2 * s3 };
        #pragma unroll
        for (int a = 0; a < 4; a++)
            #pragma unroll
            for (int b = 0; b < 4; b++)
                r[p][a * 4 + b] = hi[a] * lo[b];
    }

    float ez[4][4];
    #pragma unroll
    for (int p = 0; p < 4; p++)
        #pragma unroll
        for (int w = 0; w < 4; w++) ez[p][w] = 0.f;

    #pragma unroll
    for (int w = 0; w < 4; w++) {
        #pragma unroll
        for (int i = 0; i < 16; i++) {
            float4 a0 = As[w * 64 + i * 4 + 0];
            float4 a1 = As[w * 64 + i * 4 + 1];
            float4 a2 = As[w * 64 + i * 4 + 2];
            float4 a3 = As[w * 64 + i * 4 + 3];
            #pragma unroll
            for (int p = 0; p < 4; p++) {
                float s = a0.x * r[p][0]  + a0.y * r[p][1]  + a0.z * r[p][2]  + a0.w * r[p][3]
                        + a1.x * r[p][4]  + a1.y * r[p][5]  + a1.z * r[p][6]  + a1.w * r[p][7]
                        + a2.x * r[p][8]  + a2.y * r[p][9]  + a2.z * r[p][10] + a2.w * r[p][11]
                        + a3.x * r[p][12] + a3.y * r[p][13] + a3.z * r[p][14] + a3.w * r[p][15];
                ez[p][w] += r[p][i] * s;
            }
        }
    }

    #pragma unroll
    for (int w = 0; w < 4; w++) {
        float m = fmaxf(fmaxf(ez[0][w], ez[1][w]), fmaxf(ez[2][w], ez[3][w]));
        g_h1[w * 65025 + py * 255 + px] = 1.f / (1.f + expf(-m));
    }
}

// ---------------------------------------------------------------------------
// k_conv2: 5x5 conv (4->20) + relu + pool2 : (4,255,255) -> (20,125,125)
// ---------------------------------------------------------------------------
__global__ void __launch_bounds__(256) k_conv2(const float* __restrict__ w2,
                                               const float* __restrict__ b2) {
    int co = blockIdx.z;
    __shared__ float ws[100];
    __shared__ float tile[4][36][36];
    int tid = threadIdx.y * 16 + threadIdx.x;
    if (tid < 100) ws[tid] = w2[co * 100 + tid];

    int px0 = blockIdx.x * 16, py0 = blockIdx.y * 16;
    int iy0 = 2 * py0, ix0 = 2 * px0;
    for (int q = tid; q < 4 * 36 * 36; q += 256) {
        int ci = q / 1296, rem = q % 1296, ty = rem / 36, tx = rem % 36;
        int gy = iy0 + ty, gx = ix0 + tx;
        float v = 0.f;
        if (gy < 255 && gx < 255) v = g_h1[ci * 65025 + gy * 255 + gx];
        tile[ci][ty][tx] = v;
    }
    __syncthreads();

    int px = px0 + threadIdx.x, py = py0 + threadIdx.y;
    if (px >= 125 || py >= 125) return;

    float a00 = 0.f, a01 = 0.f, a10 = 0.f, a11 = 0.f;
    int ly = 2 * threadIdx.y, lx = 2 * threadIdx.x;
    #pragma unroll
    for (int ci = 0; ci < 4; ci++) {
        #pragma unroll
        for (int ky = 0; ky < 5; ky++) {
            #pragma unroll
            for (int kx = 0; kx < 5; kx++) {
                float wv = ws[ci * 25 + ky * 5 + kx];
                a00 += wv * tile[ci][ly + ky][lx + kx];
                a01 += wv * tile[ci][ly + ky][lx + 1 + kx];
                a10 += wv * tile[ci][ly + 1 + ky][lx + kx];
                a11 += wv * tile[ci][ly + 1 + ky][lx + 1 + kx];
            }
        }
    }
    float m = fmaxf(fmaxf(a00, a01), fmaxf(a10, a11));
    m = fmaxf(m + b2[co], 0.f);
    g_h2[co * 15625 + py * 125 + px] = m;
}

// ---------------------------------------------------------------------------
// k_conv3: 3x3 conv (20->40) + relu, fused adaptive-max 4x4 via atomicMax.
// ---------------------------------------------------------------------------
__global__ void __launch_bounds__(256) k_conv3(const float* __restrict__ w3,
                                               const float* __restrict__ b3) {
    int co = blockIdx.z;
    __shared__ float ws[180];
    __shared__ float tile[20][18][18];
    int tid = threadIdx.y * 16 + threadIdx.x;
    if (tid < 180) ws[tid] = w3[co * 180 + tid];

    int px0 = blockIdx.x * 16, py0 = blockIdx.y * 16;
    for (int q = tid; q < 20 * 18 * 18; q += 256) {
        int ci = q / 324, rem = q % 324, ty = rem / 18, tx = rem % 18;
        int gy = py0 + ty, gx = px0 + tx;
        float v = 0.f;
        if (gy < 125 && gx < 125) v = g_h2[ci * 15625 + gy * 125 + gx];
        tile[ci][ty][tx] = v;
    }
    __syncthreads();

    int px = px0 + threadIdx.x, py = py0 + threadIdx.y;
    if (px >= 123 || py >= 123) return;

    float acc = b3[co];
    #pragma unroll
    for (int ci = 0; ci < 20; ci++) {
        #pragma unroll
        for (int ky = 0; ky < 3; ky++) {
            #pragma unroll
            for (int kx = 0; kx < 3; kx++)
                acc += ws[ci * 9 + ky * 3 + kx] * tile[ci][threadIdx.y + ky][threadIdx.x + kx];
        }
    }
    acc = fmaxf(acc, 0.f);

    // adaptive-max bins over H=W=123, out=4: si = i*123/4, ei = ceil((i+1)*123/4)
    #pragma unroll
    for (int bi = 0; bi < 4; bi++) {
        int si = (bi * 123) >> 2, ei = ((bi + 1) * 123 + 3) >> 2;
        if (py < si || py >= ei) continue;
        #pragma unroll
        for (int bj = 0; bj < 4; bj++) {
            int sj = (bj * 123) >> 2, ej = ((bj + 1) * 123 + 3) >> 2;
            if (px < sj || px >= ej) continue;
            atomicMax((int*)&g_bins[co * 16 + bi * 4 + bj], __float_as_int(acc));
        }
    }
}

// ---------------------------------------------------------------------------
// k_fc: 640 -> 64 (relu) -> 10
// ---------------------------------------------------------------------------
__global__ void __launch_bounds__(64) k_fc(const float* __restrict__ w1,
                                           const float* __restrict__ b1,
                                           const float* __restrict__ w2,
                                           const float* __restrict__ b2,
                                           float* __restrict__ out) {
    __shared__ float h[640];
    __shared__ float f1[64];
    int t = threadIdx.x;
    for (int i = t; i < 640; i += 64) h[i] = g_bins[i];
    __syncthreads();
    float acc = b1[t];
    for (int j = 0; j < 640; j++) acc += w1[t * 640 + j] * h[j];
    f1[t] = fmaxf(acc, 0.f);
    __syncthreads();
    if (t < 10) {
        float a = b2[t];
        #pragma unroll
        for (int j = 0; j < 64; j++) a += w2[t * 64 + j] * f1[j];
        out[t] = a;
    }
}

// ---------------------------------------------------------------------------
extern "C" void kernel_launch(void* const* d_in, const int* in_sizes, int n_in,
                              void* d_out, int out_size) {
    const float* x   = (const float*)d_in[0];
    const float* qw  = (const float*)d_in[1];
    const float* c2w = (const float*)d_in[2];
    const float* c2b = (const float*)d_in[3];
    const float* c3w = (const float*)d_in[4];
    const float* c3b = (const float*)d_in[5];
    const float* f1w = (const float*)d_in[6];
    const float* f1b = (const float*)d_in[7];
    const float* f2w = (const float*)d_in[8];
    const float* f2b = (const float*)d_in[9];

    k_prep<<<1, 256>>>(qw);

    dim3 bq(16, 8), gq(16, 32);
    k_qconv<<<gq, bq>>>(x);

    dim3 bc(16, 16);
    dim3 g2(8, 8, 20);
    k_conv2<<<g2, bc>>>(c2w, c2b);

    dim3 g3(8, 8, 40);
    k_conv3<<<g3, bc>>>(c3w, c3b);

    k_fc<<<1, 64>>>(f1w, f1b, f2w, f2b, (float*)d_out);
}

// round 3
// speedup vs baseline: 1.6832x; 1.6832x over previous
#include <cuda_runtime.h>
#include <math.h>

// ---------------------------------------------------------------------------
// SimpleNet quanvolutional pipeline, sm_103a
// ---------------------------------------------------------------------------

__device__ float g_A[1024];          // 4 x 16 x 16
__device__ float g_h1[4 * 255 * 255];
__device__ float g_h2[20 * 125 * 125];
__device__ float g_bins[640];        // adaptive-max bins (atomicMax as int)

// ---------------------------------------------------------------------------
// k_prep: build A matrices from q_weights; zero bins.
// ---------------------------------------------------------------------------
__global__ void k_prep(const float* __restrict__ qw) {
    int t = threadIdx.x;                 // 0..255
    for (int b = t; b < 640; b += 256) ((int*)g_bins)[b] = 0;

    __shared__ float Ur[16][16], Ui[16][16];

    if (t < 16) {
        int k = t;
        float pr[16], pi[16];
        #pragma unroll
        for (int i = 0; i < 16; i++) { pr[i] = (i == k) ? 1.f : 0.f; pi[i] = 0.f; }

        for (int l = 0; l < 3; l++) {
            for (int w = 0; w < 4; w++) {
                float phi = qw[(l * 4 + w) * 3 + 0];
                float th  = qw[(l * 4 + w) * 3 + 1];
                float om  = qw[(l * 4 + w) * 3 + 2];
                float st, ct, sap, cap, sam, cam;
                sincosf(0.5f * th, &st, &ct);
                sincosf(0.5f * (phi + om), &sap, &cap);
                sincosf(0.5f * (phi - om), &sam, &cam);
                float u00r =  cap * ct, u00i = -sap * ct;
                float u01r = -cam * st, u01i = -sam * st;
                float u10r =  cam * st, u10i = -sam * st;
                float u11r =  cap * ct, u11i =  sap * ct;
                int m = 8 >> w;
                for (int i0 = 0; i0 < 16; i0++) {
                    if (i0 & m) continue;
                    int i1 = i0 | m;
                    float a0r = pr[i0], a0i = pi[i0];
                    float a1r = pr[i1], a1i = pi[i1];
                    pr[i0] = u00r * a0r - u00i * a0i + u01r * a1r - u01i * a1i;
                    pi[i0] = u00r * a0i + u00i * a0r + u01r * a1i + u01i * a1r;
                    pr[i1] = u10r * a0r - u10i * a0i + u11r * a1r - u11i * a1i;
                    pi[i1] = u10r * a0i + u10i * a0r + u11r * a1i + u11i * a1r;
                }
            }
            int r = l % 3 + 1;
            for (int w = 0; w < 4; w++) {
                int cm = 8 >> w;
                int tm = 8 >> ((w + r) & 3);
                for (int i = 0; i < 16; i++) {
                    if ((i & cm) && !(i & tm)) {
                        int j = i | tm;
                        float tr = pr[i], ti = pi[i];
                        pr[i] = pr[j]; pi[i] = pi[j];
                        pr[j] = tr;    pi[j] = ti;
                    }
                }
            }
        }
        #pragma unroll
        for (int i = 0; i < 16; i++) { Ur[i][k] = pr[i]; Ui[i][k] = pi[i]; }
    }
    __syncthreads();

    for (int e = t; e < 1024; e += 256) {
        int w = e >> 8, i = (e >> 4) & 15, j = e & 15;
        float mr = 0.f, mi = 0.f;
        #pragma unroll
        for (int kk = 0; kk < 16; kk++) {
            float z  = ((kk >> (3 - w)) & 1) ? -1.f : 1.f;
            float ar = Ur[kk][i], ai = Ui[kk][i];
            float br = Ur[kk][j], bi = Ui[kk][j];
            mr += z * (ar * br + ai * bi);
            mi += z * (ar * bi - ai * br);
        }
        int d = (__popc(j) - __popc(i)) & 3;
        float A = (d == 0) ? mr : (d == 1) ? mi : (d == 2) ? -mr : -mi;
        g_A[e] = A;
    }
}

// ---------------------------------------------------------------------------
// k_qconv: qsim + sigmoid + pool2 -> g_h1[4][255][255]
// ---------------------------------------------------------------------------
__global__ void __launch_bounds__(128) k_qconv(const float* __restrict__ img) {
    __shared__ __align__(16) float4 As[256];  // 4 * 16 rows * 4 float4
    {
        int tid = threadIdx.y * 16 + threadIdx.x;
        for (int q = tid; q < 256; q += 128) As[q] = ((const float4*)g_A)[q];
    }
    __syncthreads();

    int px = blockIdx.x * 16 + threadIdx.x;
    int py = blockIdx.y * 8 + threadIdx.y;
    if (px >= 255 || py >= 255) return;

    float cc[9], ss[9];
    int y0 = 2 * py, x0 = 2 * px;
    #pragma unroll
    for (int d = 0; d < 9; d++) {
        int dy = d / 3, dx = d % 3;
        float v = 0.5f * img[(y0 + dy) * 512 + (x0 + dx)];
        __sincosf(v, &ss[d], &cc[d]);
    }

    float r[4][16];
    #pragma unroll
    for (int p = 0; p < 4; p++) {
        int dy = p >> 1, dx = p & 1;
        int ia = dy * 3 + dx, ib = ia + 1, ic = ia + 3, id = ia + 4;
        float c0 = cc[ia], s0 = ss[ia], c1 = cc[ib], s1 = ss[ib];
        float c2 = cc[ic], s2 = ss[ic], c3 = cc[id], s3 = ss[id];
        float hi[4] = { c0 * c1, c0 * s1, s0 * c1, s0 * s1 };
        float lo[4] = { c2 * c3, c2 * s3, s2 * c3, s2 * s3 };
        #pragma unroll
        for (int a = 0; a < 4; a++)
            #pragma unroll
            for (int b = 0; b < 4; b++)
                r[p][a * 4 + b] = hi[a] * lo[b];
    }

    float ez[4][4];
    #pragma unroll
    for (int p = 0; p < 4; p++)
        #pragma unroll
        for (int w = 0; w < 4; w++) ez[p][w] = 0.f;

    #pragma unroll
    for (int w = 0; w < 4; w++) {
        #pragma unroll
        for (int i = 0; i < 16; i++) {
            float4 a0 = As[w * 64 + i * 4 + 0];
            float4 a1 = As[w * 64 + i * 4 + 1];
            float4 a2 = As[w * 64 + i * 4 + 2];
            float4 a3 = As[w * 64 + i * 4 + 3];
            #pragma unroll
            for (int p = 0; p < 4; p++) {
                float s = a0.x * r[p][0]  + a0.y * r[p][1]  + a0.z * r[p][2]  + a0.w * r[p][3]
                        + a1.x * r[p][4]  + a1.y * r[p][5]  + a1.z * r[p][6]  + a1.w * r[p][7]
                        + a2.x * r[p][8]  + a2.y * r[p][9]  + a2.z * r[p][10] + a2.w * r[p][11]
                        + a3.x * r[p][12] + a3.y * r[p][13] + a3.z * r[p][14] + a3.w * r[p][15];
                ez[p][w] += r[p][i] * s;
            }
        }
    }

    #pragma unroll
    for (int w = 0; w < 4; w++) {
        float m = fmaxf(fmaxf(ez[0][w], ez[1][w]), fmaxf(ez[2][w], ez[3][w]));
        g_h1[w * 65025 + py * 255 + px] = 1.f / (1.f + __expf(-m));
    }
}

// ---------------------------------------------------------------------------
// k_conv2: 5x5 conv (4->20) + relu + pool2 : (4,255,255) -> (20,125,125)
// Each thread: 1 pooled pixel (2x2 pre-pool) x 4 output channels.
// Grid (8,8,5); block 16x16.
// ---------------------------------------------------------------------------
__global__ void __launch_bounds__(256) k_conv2(const float* __restrict__ w2,
                                               const float* __restrict__ b2) {
    int cog = blockIdx.z;                    // co = cog*4 .. cog*4+3
    __shared__ float ws[4][100];
    __shared__ __align__(16) float tile[4][36][36];
    int tx = threadIdx.x, ty = threadIdx.y;
    int tid = ty * 16 + tx;

    for (int q = tid; q < 400; q += 256) {
        int co = q / 100, r = q % 100;
        ws[co][r] = w2[(cog * 4 + co) * 100 + r];
    }

    int px0 = blockIdx.x * 16, py0 = blockIdx.y * 16;
    int iy0 = 2 * py0, ix0 = 2 * px0;
    for (int q = tid; q < 4 * 1296; q += 256) {
        int ci = q / 1296, rem = q % 1296, ry = rem / 36, rx = rem % 36;
        int gy = iy0 + ry, gx = ix0 + rx;
        float v = 0.f;
        if (gy < 255 && gx < 255) v = g_h1[ci * 65025 + gy * 255 + gx];
        tile[ci][ry][rx] = v;
    }
    __syncthreads();

    int px = px0 + tx, py = py0 + ty;
    if (px >= 125 || py >= 125) return;

    float acc[4][4];
    #pragma unroll
    for (int co = 0; co < 4; co++)
        #pragma unroll
        for (int p = 0; p < 4; p++) acc[co][p] = 0.f;

    int ly = 2 * ty, lx = 2 * tx;
    #pragma unroll
    for (int ci = 0; ci < 4; ci++) {
        float patch[6][6];
        #pragma unroll
        for (int r = 0; r < 6; r++) {
            const float2* rp = (const float2*)&tile[ci][ly + r][lx];
            float2 v0 = rp[0], v1 = rp[1], v2 = rp[2];
            patch[r][0] = v0.x; patch[r][1] = v0.y;
            patch[r][2] = v1.x; patch[r][3] = v1.y;
            patch[r][4] = v2.x; patch[r][5] = v2.y;
        }
        #pragma unroll
        for (int co = 0; co < 4; co++) {
            #pragma unroll
            for (int ky = 0; ky < 5; ky++) {
                #pragma unroll
                for (int kx = 0; kx < 5; kx++) {
                    float wv = ws[co][ci * 25 + ky * 5 + kx];
                    acc[co][0] += wv * patch[ky][kx];
                    acc[co][1] += wv * patch[ky][kx + 1];
                    acc[co][2] += wv * patch[ky + 1][kx];
                    acc[co][3] += wv * patch[ky + 1][kx + 1];
                }
            }
        }
    }
    #pragma unroll
    for (int co = 0; co < 4; co++) {
        float m = fmaxf(fmaxf(acc[co][0], acc[co][1]), fmaxf(acc[co][2], acc[co][3]));
        m = fmaxf(m + b2[cog * 4 + co], 0.f);
        g_h2[(cog * 4 + co) * 15625 + py * 125 + px] = m;
    }
}

// ---------------------------------------------------------------------------
// k_conv3: 3x3 conv (20->40) + relu + adaptive-max.
// Each thread: 2x2 output pixels x 4 output channels. Block covers 32x32 px.
// Grid (4,4,10); block 16x16. ci processed in 4 chunks of 5 (smem).
// Adaptive bins over 123: bin b = [floor(b*123/4), ceil((b+1)*123/4))
//   = [0,31) [30,62) [61,93) [92,123); overlap rows 30,61,92 belong to the
//   floor-bin AND the NEXT bin (y >= si(bi+1)).
// ---------------------------------------------------------------------------
__global__ void __launch_bounds__(256) k_conv3(const float* __restrict__ w3,
                                               const float* __restrict__ b3) {
    int cog = blockIdx.z;                    // co = cog*4 .. +3
    __shared__ float ws[4][180];
    __shared__ __align__(16) float tile[5][34][34];
    __shared__ int sbins[4][16];
    int tx = threadIdx.x, ty = threadIdx.y;
    int tid = ty * 16 + tx;

    for (int q = tid; q < 720; q += 256) {
        int co = q / 180, r = q % 180;
        ws[co][r] = w3[(cog * 4 + co) * 180 + r];
    }
    if (tid < 64) ((int*)sbins)[tid] = 0;

    int px0 = blockIdx.x * 32, py0 = blockIdx.y * 32;
    int ly = 2 * ty, lx = 2 * tx;

    float acc[4][4];
    #pragma unroll
    for (int co = 0; co < 4; co++)
        #pragma unroll
        for (int p = 0; p < 4; p++) acc[co][p] = 0.f;

    for (int c4 = 0; c4 < 4; c4++) {
        __syncthreads();
        for (int q = tid; q < 5 * 1156; q += 256) {
            int cil = q / 1156, rem = q % 1156, ry = rem / 34, rx = rem % 34;
            int gy = py0 + ry, gx = px0 + rx;
            float v = 0.f;
            if (gy < 125 && gx < 125) v = g_h2[(c4 * 5 + cil) * 15625 + gy * 125 + gx];
            tile[cil][ry][rx] = v;
        }
        __syncthreads();

        #pragma unroll
        for (int cil = 0; cil < 5; cil++) {
            int ci = c4 * 5 + cil;
            float patch[4][4];
            #pragma unroll
            for (int r = 0; r < 4; r++) {
                const float2* rp = (const float2*)&tile[cil][ly + r][lx];
                float2 v0 = rp[0], v1 = rp[1];
                patch[r][0] = v0.x; patch[r][1] = v0.y;
                patch[r][2] = v1.x; patch[r][3] = v1.y;
            }
            #pragma unroll
            for (int co = 0; co < 4; co++) {
                #pragma unroll
                for (int ky = 0; ky < 3; ky++) {
                    #pragma unroll
                    for (int kx = 0; kx < 3; kx++) {
                        float wv = ws[co][ci * 9 + ky * 3 + kx];
                        acc[co][0] += wv * patch[ky][kx];
                        acc[co][1] += wv * patch[ky][kx + 1];
                        acc[co][2] += wv * patch[ky + 1][kx];
                        acc[co][3] += wv * patch[ky + 1][kx + 1];
                    }
                }
            }
        }
    }

    // epilogue: relu + bias, reduce into block-local bins, then to global
    #pragma unroll
    for (int co = 0; co < 4; co++) {
        float bb = b3[cog * 4 + co];
        #pragma unroll
        for (int dy = 0; dy < 2; dy++) {
            #pragma unroll
            for (int dx = 0; dx < 2; dx++) {
                int gy = py0 + ly + dy, gx = px0 + lx + dx;
                if (gy >= 123 || gx >= 123) continue;
                float v = fmaxf(acc[co][dy * 2 + dx] + bb, 0.f);
                int iv = __float_as_int(v);
                int bi = (gy * 4) / 123; if (bi > 3) bi = 3;
                int bj = (gx * 4) / 123; if (bj > 3) bj = 3;
                // overlap: pixel also belongs to the NEXT bin when
                // gy >= si(bi+1) = floor((bi+1)*123/4)
                bool oy = (bi < 3) && (gy >= (((bi + 1) * 123) >> 2));
                bool ox = (bj < 3) && (gx >= (((bj + 1) * 123) >> 2));
                atomicMax(&sbins[co][bi * 4 + bj], iv);
                if (oy) atomicMax(&sbins[co][(bi + 1) * 4 + bj], iv);
                if (ox) atomicMax(&sbins[co][bi * 4 + (bj + 1)], iv);
                if (oy && ox) atomicMax(&sbins[co][(bi + 1) * 4 + (bj + 1)], iv);
            }
        }
    }
    __syncthreads();
    if (tid < 64) {
        int co = tid >> 4, b = tid & 15;
        atomicMax((int*)&g_bins[(cog * 4 + co) * 16 + b], sbins[co][b]);
    }
}

// ---------------------------------------------------------------------------
// k_fc: 640 -> 64 (relu) -> 10. One block, 256 threads (8 warps).
// ---------------------------------------------------------------------------
__global__ void __launch_bounds__(256) k_fc(const float* __restrict__ w1,
                                            const float* __restrict__ b1,
                                            const float* __restrict__ w2,
                                            const float* __restrict__ b2,
                                            float* __restrict__ out) {
    __shared__ float h[640];
    __shared__ float f1[64];
    int t = threadIdx.x;
    for (int i = t; i < 640; i += 256) h[i] = g_bins[i];
    __syncthreads();

    int warp = t >> 5, lane = t & 31;
    #pragma unroll
    for (int k = 0; k < 8; k++) {
        int n = warp * 8 + k;
        float s = 0.f;
        for (int j = lane; j < 640; j += 32) s += w1[n * 640 + j] * h[j];
        s += __shfl_xor_sync(0xffffffffu, s, 16);
        s += __shfl_xor_sync(0xffffffffu, s, 8);
        s += __shfl_xor_sync(0xffffffffu, s, 4);
        s += __shfl_xor_sync(0xffffffffu, s, 2);
        s += __shfl_xor_sync(0xffffffffu, s, 1);
        if (lane == 0) f1[n] = fmaxf(s + b1[n], 0.f);
    }
    __syncthreads();
    if (t < 10) {
        float a = b2[t];
        #pragma unroll
        for (int j = 0; j < 64; j++) a += w2[t * 64 + j] * f1[j];
        out[t] = a;
    }
}

// ---------------------------------------------------------------------------
extern "C" void kernel_launch(void* const* d_in, const int* in_sizes, int n_in,
                              void* d_out, int out_size) {
    const float* x   = (const float*)d_in[0];
    const float* qw  = (const float*)d_in[1];
    const float* c2w = (const float*)d_in[2];
    const float* c2b = (const float*)d_in[3];
    const float* c3w = (const float*)d_in[4];
    const float* c3b = (const float*)d_in[5];
    const float* f1w = (const float*)d_in[6];
    const float* f1b = (const float*)d_in[7];
    const float* f2w = (const float*)d_in[8];
    const float* f2b = (const float*)d_in[9];

    k_prep<<<1, 256>>>(qw);

    dim3 bq(16, 8), gq(16, 32);
    k_qconv<<<gq, bq>>>(x);

    dim3 bc(16, 16);
    dim3 g2(8, 8, 5);
    k_conv2<<<g2, bc>>>(c2w, c2b);

    dim3 g3(4, 4, 10);
    k_conv3<<<g3, bc>>>(c3w, c3b);

    k_fc<<<1, 256>>>(f1w, f1b, f2w, f2b, (float*)d_out);
}

// round 5
// speedup vs baseline: 2.1250x; 1.2624x over previous
#include <cuda_runtime.h>
#include <math.h>

// ---------------------------------------------------------------------------
// SimpleNet quanvolutional pipeline, sm_103a
// Layouts padded for float4 access:
//   g_h1: [4][255][256]  (row stride 256)
//   g_h2: [20][125][128] (row stride 128)
// ---------------------------------------------------------------------------

__device__ float g_U[512];                 // [2][16][16]: Wr rows then Wi rows
__device__ float g_h1[4 * 255 * 256];
__device__ float g_h2[20 * 125 * 128];
__device__ float g_bins[640];              // adaptive-max bins (atomicMax as int)

#define H1_STRIDE 256
#define H1_PLANE  (255 * 256)
#define H2_STRIDE 128
#define H2_PLANE  (125 * 128)

// ---------------------------------------------------------------------------
// k_prep: simulate weight circuit -> U (16x16 complex), then export
// W[k][j] = U[k][j] * (-i)^popc(j)  (phases of the RX-encoded input state,
// psi_in[j] = (-i)^popc(j) * r_j with r real). Zero the adaptive-max bins.
// ---------------------------------------------------------------------------
__global__ void k_prep(const float* __restrict__ qw) {
    int t = threadIdx.x;                 // 0..255
    for (int b = t; b < 640; b += 256) ((int*)g_bins)[b] = 0;

    __shared__ float Ur[16][16], Ui[16][16];

    if (t < 16) {
        int k = t;
        float pr[16], pi[16];
        #pragma unroll
        for (int i = 0; i < 16; i++) { pr[i] = (i == k) ? 1.f : 0.f; pi[i] = 0.f; }

        for (int l = 0; l < 3; l++) {
            for (int w = 0; w < 4; w++) {
                float phi = qw[(l * 4 + w) * 3 + 0];
                float th  = qw[(l * 4 + w) * 3 + 1];
                float om  = qw[(l * 4 + w) * 3 + 2];
                float st, ct, sap, cap, sam, cam;
                sincosf(0.5f * th, &st, &ct);
                sincosf(0.5f * (phi + om), &sap, &cap);
                sincosf(0.5f * (phi - om), &sam, &cam);
                float u00r =  cap * ct, u00i = -sap * ct;
                float u01r = -cam * st, u01i = -sam * st;
                float u10r =  cam * st, u10i = -sam * st;
                float u11r =  cap * ct, u11i =  sap * ct;
                int m = 8 >> w;
                for (int i0 = 0; i0 < 16; i0++) {
                    if (i0 & m) continue;
                    int i1 = i0 | m;
                    float a0r = pr[i0], a0i = pi[i0];
                    float a1r = pr[i1], a1i = pi[i1];
                    pr[i0] = u00r * a0r - u00i * a0i + u01r * a1r - u01i * a1i;
                    pi[i0] = u00r * a0i + u00i * a0r + u01r * a1i + u01i * a1r;
                    pr[i1] = u10r * a0r - u10i * a0i + u11r * a1r - u11i * a1i;
                    pi[i1] = u10r * a0i + u10i * a0r + u11r * a1i + u11i * a1r;
                }
            }
            int r = l % 3 + 1;
            for (int w = 0; w < 4; w++) {
                int cm = 8 >> w;
                int tm = 8 >> ((w + r) & 3);
                for (int i = 0; i < 16; i++) {
                    if ((i & cm) && !(i & tm)) {
                        int j = i | tm;
                        float tr = pr[i], ti = pi[i];
                        pr[i] = pr[j]; pi[i] = pi[j];
                        pr[j] = tr;    pi[j] = ti;
                    }
                }
            }
        }
        // column k of U
        #pragma unroll
        for (int i = 0; i < 16; i++) { Ur[i][k] = pr[i]; Ui[i][k] = pi[i]; }
    }
    __syncthreads();

    // export W rows: W[i][j] = U[i][j] * (-i)^popc(j)
    // d=0: (ur, ui); d=1: (ui, -ur); d=2: (-ur, -ui); d=3: (-ui, ur)
    int i = t >> 4, j = t & 15;
    float ur = Ur[i][j], ui = Ui[i][j];
    int d = __popc(j) & 3;
    float wr = (d == 0) ? ur : (d == 1) ? ui : (d == 2) ? -ur : -ui;
    float wi = (d == 0) ? ui : (d == 1) ? -ur : (d == 2) ? -ui : ur;
    g_U[t]       = wr;
    g_U[256 + t] = wi;
}

// ---------------------------------------------------------------------------
// k_qconv: per pooled pixel compute 4 patches: psi = W r, probs, ez; max-pool,
// sigmoid, store g_h1. ez_w = sum_k (+/-) |psi_k|^2 with sign from bit of k.
// ---------------------------------------------------------------------------
__global__ void __launch_bounds__(128) k_qconv(const float* __restrict__ img) {
    __shared__ __align__(16) float4 Us[128];   // Wr rows (64 f4) then Wi rows
    {
        int tid = threadIdx.y * 16 + threadIdx.x;
        if (tid < 128) Us[tid] = ((const float4*)g_U)[tid];
    }
    __syncthreads();

    int px = blockIdx.x * 16 + threadIdx.x;
    int py = blockIdx.y * 8 + threadIdx.y;
    if (px >= 255 || py >= 255) return;

    float cc[9], ss[9];
    int y0 = 2 * py, x0 = 2 * px;
    #pragma unroll
    for (int d = 0; d < 9; d++) {
        int dy = d / 3, dx = d % 3;
        float v = 0.5f * img[(y0 + dy) * 512 + (x0 + dx)];
        __sincosf(v, &ss[d], &cc[d]);
    }

    float r[4][16];
    #pragma unroll
    for (int p = 0; p < 4; p++) {
        int dy = p >> 1, dx = p & 1;
        int ia = dy * 3 + dx, ib = ia + 1, ic = ia + 3, id = ia + 4;
        float c0 = cc[ia], s0 = ss[ia], c1 = cc[ib], s1 = ss[ib];
        float c2 = cc[ic], s2 = ss[ic], c3 = cc[id], s3 = ss[id];
        float hi[4] = { c0 * c1, c0 * s1, s0 * c1, s0 * s1 };
        float lo[4] = { c2 * c3, c2 * s3, s2 * c3, s2 * s3 };
        #pragma unroll
        for (int a = 0; a < 4; a++)
            #pragma unroll
            for (int b = 0; b < 4; b++)
                r[p][a * 4 + b] = hi[a] * lo[b];
    }

    float ez[4][4];
    #pragma unroll
    for (int p = 0; p < 4; p++)
        #pragma unroll
        for (int w = 0; w < 4; w++) ez[p][w] = 0.f;

    #pragma unroll
    for (int k = 0; k < 16; k++) {
        float4 u0 = Us[k * 4 + 0], u1 = Us[k * 4 + 1];
        float4 u2 = Us[k * 4 + 2], u3 = Us[k * 4 + 3];
        float4 v0 = Us[64 + k * 4 + 0], v1 = Us[64 + k * 4 + 1];
        float4 v2 = Us[64 + k * 4 + 2], v3 = Us[64 + k * 4 + 3];
        #pragma unroll
        for (int p = 0; p < 4; p++) {
            float sr = u0.x * r[p][0]  + u0.y * r[p][1]  + u0.z * r[p][2]  + u0.w * r[p][3]
                     + u1.x * r[p][4]  + u1.y * r[p][5]  + u1.z * r[p][6]  + u1.w * r[p][7]
                     + u2.x * r[p][8]  + u2.y * r[p][9]  + u2.z * r[p][10] + u2.w * r[p][11]
                     + u3.x * r[p][12] + u3.y * r[p][13] + u3.z * r[p][14] + u3.w * r[p][15];
            float si = v0.x * r[p][0]  + v0.y * r[p][1]  + v0.z * r[p][2]  + v0.w * r[p][3]
                     + v1.x * r[p][4]  + v1.y * r[p][5]  + v1.z * r[p][6]  + v1.w * r[p][7]
                     + v2.x * r[p][8]  + v2.y * r[p][9]  + v2.z * r[p][10] + v2.w * r[p][11]
                     + v3.x * r[p][12] + v3.y * r[p][13] + v3.z * r[p][14] + v3.w * r[p][15];
            float pk = sr * sr + si * si;
            ez[p][0] += (k & 8) ? -pk : pk;
            ez[p][1] += (k & 4) ? -pk : pk;
            ez[p][2] += (k & 2) ? -pk : pk;
            ez[p][3] += (k & 1) ? -pk : pk;
        }
    }

    #pragma unroll
    for (int w = 0; w < 4; w++) {
        float m = fmaxf(fmaxf(ez[0][w], ez[1][w]), fmaxf(ez[2][w], ez[3][w]));
        g_h1[w * H1_PLANE + py * H1_STRIDE + px] = 1.f / (1.f + __expf(-m));
    }
}

// ---------------------------------------------------------------------------
// k_conv2: 5x5 conv (4->20) + relu + pool2 : -> g_h2 (padded).
// Thread: 1 pooled px x 2 co. Grid (8,8,10); block 16x16.
// ---------------------------------------------------------------------------
__global__ void __launch_bounds__(256) k_conv2(const float* __restrict__ w2,
                                               const float* __restrict__ b2) {
    int cog = blockIdx.z;                    // co = cog*2, cog*2+1
    __shared__ float ws[2][100];
    __shared__ __align__(16) float tile[4][36][36];
    int tx = threadIdx.x, ty = threadIdx.y;
    int tid = ty * 16 + tx;

    if (tid < 200) {
        int co = tid / 100, rr = tid % 100;
        ws[co][rr] = w2[(cog * 2 + co) * 100 + rr];
    }

    int px0 = blockIdx.x * 16, py0 = blockIdx.y * 16;
    int iy0 = 2 * py0, ix0 = 2 * px0;
    // fill: 4 ci x 36 rows x 9 float4
    for (int q = tid; q < 4 * 36 * 9; q += 256) {
        int ci = q / 324, rem = q % 324, ry = rem / 9, f4 = rem % 9;
        int gy = iy0 + ry, gx = ix0 + f4 * 4;
        float4 v = make_float4(0.f, 0.f, 0.f, 0.f);
        if (gy < 255) {
            const float* src = &g_h1[ci * H1_PLANE + gy * H1_STRIDE + gx];
            if (gx + 3 < 255) {
                v = *(const float4*)src;
            } else {
                if (gx + 0 < 255) v.x = src[0];
                if (gx + 1 < 255) v.y = src[1];
                if (gx + 2 < 255) v.z = src[2];
                if (gx + 3 < 255) v.w = src[3];
            }
        }
        *(float4*)&tile[ci][ry][f4 * 4] = v;
    }
    __syncthreads();

    int px = px0 + tx, py = py0 + ty;
    if (px >= 125 || py >= 125) return;

    float acc[2][4];
    #pragma unroll
    for (int co = 0; co < 2; co++)
        #pragma unroll
        for (int p = 0; p < 4; p++) acc[co][p] = 0.f;

    int ly = 2 * ty, lx = 2 * tx;
    #pragma unroll
    for (int ci = 0; ci < 4; ci++) {
        float patch[6][6];
        #pragma unroll
        for (int rr = 0; rr < 6; rr++) {
            const float2* rp = (const float2*)&tile[ci][ly + rr][lx];
            float2 v0 = rp[0], v1 = rp[1], v2 = rp[2];
            patch[rr][0] = v0.x; patch[rr][1] = v0.y;
            patch[rr][2] = v1.x; patch[rr][3] = v1.y;
            patch[rr][4] = v2.x; patch[rr][5] = v2.y;
        }
        #pragma unroll
        for (int co = 0; co < 2; co++) {
            #pragma unroll
            for (int ky = 0; ky < 5; ky++) {
                #pragma unroll
                for (int kx = 0; kx < 5; kx++) {
                    float wv = ws[co][ci * 25 + ky * 5 + kx];
                    acc[co][0] += wv * patch[ky][kx];
                    acc[co][1] += wv * patch[ky][kx + 1];
                    acc[co][2] += wv * patch[ky + 1][kx];
                    acc[co][3] += wv * patch[ky + 1][kx + 1];
                }
            }
        }
    }
    #pragma unroll
    for (int co = 0; co < 2; co++) {
        float m = fmaxf(fmaxf(acc[co][0], acc[co][1]), fmaxf(acc[co][2], acc[co][3]));
        m = fmaxf(m + b2[cog * 2 + co], 0.f);
        g_h2[(cog * 2 + co) * H2_PLANE + py * H2_STRIDE + px] = m;
    }
}

// ---------------------------------------------------------------------------
// k_conv3: 3x3 conv (20->40) + relu + adaptive-max.
// Thread: 2x2 px x 1 co. Block 16x16 covers 32x32 px. Grid (4,4,40).
// Bins over 123: bin b = [floor(b*123/4), ceil((b+1)*123/4)); overlap rows
// 30,61,92 also belong to the NEXT bin.
// ---------------------------------------------------------------------------
__global__ void __launch_bounds__(256) k_conv3(const float* __restrict__ w3,
                                               const float* __restrict__ b3) {
    int co = blockIdx.z;
    __shared__ float ws[180];
    __shared__ __align__(16) float tile[5][34][36];   // row padded to 36
    __shared__ int sbins[16];
    int tx = threadIdx.x, ty = threadIdx.y;
    int tid = ty * 16 + tx;

    if (tid < 180) ws[tid] = w3[co * 180 + tid];
    if (tid < 16) sbins[tid] = 0;

    int px0 = blockIdx.x * 32, py0 = blockIdx.y * 32;
    int ly = 2 * ty, lx = 2 * tx;

    float acc[4] = {0.f, 0.f, 0.f, 0.f};

    for (int c4 = 0; c4 < 4; c4++) {
        __syncthreads();
        // fill 5 ci x 34 rows x 9 float4 (cols 0..35, tile padded)
        for (int q = tid; q < 5 * 34 * 9; q += 256) {
            int cil = q / 306, rem = q % 306, ry = rem / 9, f4 = rem % 9;
            int gy = py0 + ry, gx = px0 + f4 * 4;
            float4 v = make_float4(0.f, 0.f, 0.f, 0.f);
            if (gy < 125) {
                const float* src = &g_h2[(c4 * 5 + cil) * H2_PLANE + gy * H2_STRIDE + gx];
                if (gx + 3 < 125) {
                    v = *(const float4*)src;
                } else {
                    if (gx + 0 < 125) v.x = src[0];
                    if (gx + 1 < 125) v.y = src[1];
                    if (gx + 2 < 125) v.z = src[2];
                    if (gx + 3 < 125) v.w = src[3];
                }
            }
            *(float4*)&tile[cil][ry][f4 * 4] = v;
        }
        __syncthreads();

        #pragma unroll
        for (int cil = 0; cil < 5; cil++) {
            int ci = c4 * 5 + cil;
            float patch[4][4];
            #pragma unroll
            for (int rr = 0; rr < 4; rr++) {
                const float2* rp = (const float2*)&tile[cil][ly + rr][lx];
                float2 v0 = rp[0], v1 = rp[1];
                patch[rr][0] = v0.x; patch[rr][1] = v0.y;
                patch[rr][2] = v1.x; patch[rr][3] = v1.y;
            }
            #pragma unroll
            for (int ky = 0; ky < 3; ky++) {
                #pragma unroll
                for (int kx = 0; kx < 3; kx++) {
                    float wv = ws[ci * 9 + ky * 3 + kx];
                    acc[0] += wv * patch[ky][kx];
                    acc[1] += wv * patch[ky][kx + 1];
                    acc[2] += wv * patch[ky + 1][kx];
                    acc[3] += wv * patch[ky + 1][kx + 1];
                }
            }
        }
    }

    float bb = b3[co];
    #pragma unroll
    for (int dy = 0; dy < 2; dy++) {
        #pragma unroll
        for (int dx = 0; dx < 2; dx++) {
            int gy = py0 + ly + dy, gx = px0 + lx + dx;
            if (gy >= 123 || gx >= 123) continue;
            float v = fmaxf(acc[dy * 2 + dx] + bb, 0.f);
            int iv = __float_as_int(v);
            int bi = (gy * 4) / 123; if (bi > 3) bi = 3;
            int bj = (gx * 4) / 123; if (bj > 3) bj = 3;
            bool oy = (bi < 3) && (gy >= (((bi + 1) * 123) >> 2));
            bool ox = (bj < 3) && (gx >= (((bj + 1) * 123) >> 2));
            atomicMax(&sbins[bi * 4 + bj], iv);
            if (oy) atomicMax(&sbins[(bi + 1) * 4 + bj], iv);
            if (ox) atomicMax(&sbins[bi * 4 + (bj + 1)], iv);
            if (oy && ox) atomicMax(&sbins[(bi + 1) * 4 + (bj + 1)], iv);
        }
    }
    __syncthreads();
    if (tid < 16) atomicMax((int*)&g_bins[co * 16 + tid], sbins[tid]);
}

// ---------------------------------------------------------------------------
// k_fc: 640 -> 64 (relu) -> 10. One block, 256 threads (8 warps).
// ---------------------------------------------------------------------------
__global__ void __launch_bounds__(256) k_fc(const float* __restrict__ w1,
                                            const float* __restrict__ b1,
                                            const float* __restrict__ w2,
                                            const float* __restrict__ b2,
                                            float* __restrict__ out) {
    __shared__ float h[640];
    __shared__ float f1[64];
    int t = threadIdx.x;
    for (int i = t; i < 640; i += 256) h[i] = g_bins[i];
    __syncthreads();

    int warp = t >> 5, lane = t & 31;
    #pragma unroll
    for (int k = 0; k < 8; k++) {
        int n = warp * 8 + k;
        float s = 0.f;
        for (int j = lane; j < 640; j += 32) s += w1[n * 640 + j] * h[j];
        s += __shfl_xor_sync(0xffffffffu, s, 16);
        s += __shfl_xor_sync(0xffffffffu, s, 8);
        s += __shfl_xor_sync(0xffffffffu, s, 4);
        s += __shfl_xor_sync(0xffffffffu, s, 2);
        s += __shfl_xor_sync(0xffffffffu, s, 1);
        if (lane == 0) f1[n] = fmaxf(s + b1[n], 0.f);
    }
    __syncthreads();
    if (t < 10) {
        float a = b2[t];
        #pragma unroll
        for (int j = 0; j < 64; j++) a += w2[t * 64 + j] * f1[j];
        out[t] = a;
    }
}

// ---------------------------------------------------------------------------
extern "C" void kernel_launch(void* const* d_in, const int* in_sizes, int n_in,
                              void* d_out, int out_size) {
    const float* x   = (const float*)d_in[0];
    const float* qw  = (const float*)d_in[1];
    const float* c2w = (const float*)d_in[2];
    const float* c2b = (const float*)d_in[3];
    const float* c3w = (const float*)d_in[4];
    const float* c3b = (const float*)d_in[5];
    const float* f1w = (const float*)d_in[6];
    const float* f1b = (const float*)d_in[7];
    const float* f2w = (const float*)d_in[8];
    const float* f2b = (const float*)d_in[9];

    k_prep<<<1, 256>>>(qw);

    dim3 bq(16, 8), gq(16, 32);
    k_qconv<<<gq, bq>>>(x);

    dim3 bc(16, 16);
    dim3 g2(8, 8, 10);
    k_conv2<<<g2, bc>>>(c2w, c2b);

    dim3 g3(4, 4, 40);
    k_conv3<<<g3, bc>>>(c3w, c3b);

    k_fc<<<1, 256>>>(f1w, f1b, f2w, f2b, (float*)d_out);
}

// round 6
// speedup vs baseline: 2.2351x; 1.0518x over previous
#include <cuda_runtime.h>
#include <math.h>

// ---------------------------------------------------------------------------
// SimpleNet quanvolutional pipeline, sm_103a
// Layouts padded for float4 access:
//   g_h1: [4][255][256]  (row stride 256)
//   g_h2: [20][125][128] (row stride 128)
// ---------------------------------------------------------------------------

__device__ float g_U[512];                 // [2][16][16]: Wr rows then Wi rows
__device__ float g_h1[4 * 255 * 256];
__device__ float g_h2[20 * 125 * 128];
__device__ float g_bins[640];              // adaptive-max bins (atomicMax as int)

#define H1_STRIDE 256
#define H1_PLANE  (255 * 256)
#define H2_STRIDE 128
#define H2_PLANE  (125 * 128)

// ---------------------------------------------------------------------------
// k_prep: simulate weight circuit -> U (16x16 complex), then export
// W[k][j] = U[k][j] * (-i)^popc(j). Zero the adaptive-max bins.
// ---------------------------------------------------------------------------
__global__ void k_prep(const float* __restrict__ qw) {
    int t = threadIdx.x;                 // 0..255
    for (int b = t; b < 640; b += 256) ((int*)g_bins)[b] = 0;

    __shared__ float Ur[16][16], Ui[16][16];

    if (t < 16) {
        int k = t;
        float pr[16], pi[16];
        #pragma unroll
        for (int i = 0; i < 16; i++) { pr[i] = (i == k) ? 1.f : 0.f; pi[i] = 0.f; }

        for (int l = 0; l < 3; l++) {
            for (int w = 0; w < 4; w++) {
                float phi = qw[(l * 4 + w) * 3 + 0];
                float th  = qw[(l * 4 + w) * 3 + 1];
                float om  = qw[(l * 4 + w) * 3 + 2];
                float st, ct, sap, cap, sam, cam;
                sincosf(0.5f * th, &st, &ct);
                sincosf(0.5f * (phi + om), &sap, &cap);
                sincosf(0.5f * (phi - om), &sam, &cam);
                float u00r =  cap * ct, u00i = -sap * ct;
                float u01r = -cam * st, u01i = -sam * st;
                float u10r =  cam * st, u10i = -sam * st;
                float u11r =  cap * ct, u11i =  sap * ct;
                int m = 8 >> w;
                for (int i0 = 0; i0 < 16; i0++) {
                    if (i0 & m) continue;
                    int i1 = i0 | m;
                    float a0r = pr[i0], a0i = pi[i0];
                    float a1r = pr[i1], a1i = pi[i1];
                    pr[i0] = u00r * a0r - u00i * a0i + u01r * a1r - u01i * a1i;
                    pi[i0] = u00r * a0i + u00i * a0r + u01r * a1i + u01i * a1r;
                    pr[i1] = u10r * a0r - u10i * a0i + u11r * a1r - u11i * a1i;
                    pi[i1] = u10r * a0i + u10i * a0r + u11r * a1i + u11i * a1r;
                }
            }
            int r = l % 3 + 1;
            for (int w = 0; w < 4; w++) {
                int cm = 8 >> w;
                int tm = 8 >> ((w + r) & 3);
                for (int i = 0; i < 16; i++) {
                    if ((i & cm) && !(i & tm)) {
                        int j = i | tm;
                        float tr = pr[i], ti = pi[i];
                        pr[i] = pr[j]; pi[i] = pi[j];
                        pr[j] = tr;    pi[j] = ti;
                    }
                }
            }
        }
        #pragma unroll
        for (int i = 0; i < 16; i++) { Ur[i][k] = pr[i]; Ui[i][k] = pi[i]; }
    }
    __syncthreads();

    int i = t >> 4, j = t & 15;
    float ur = Ur[i][j], ui = Ui[i][j];
    int d = __popc(j) & 3;
    float wr = (d == 0) ? ur : (d == 1) ? ui : (d == 2) ? -ur : -ui;
    float wi = (d == 0) ? ui : (d == 1) ? -ur : (d == 2) ? -ui : ur;
    g_U[t]       = wr;
    g_U[256 + t] = wi;
}

// ---------------------------------------------------------------------------
// k_qconv: per pooled pixel compute 4 patches: psi = W r, probs, ez; max-pool,
// sigmoid, store g_h1.
// ---------------------------------------------------------------------------
__global__ void __launch_bounds__(128) k_qconv(const float* __restrict__ img) {
    __shared__ __align__(16) float4 Us[128];   // Wr rows (64 f4) then Wi rows
    {
        int tid = threadIdx.y * 16 + threadIdx.x;
        if (tid < 128) Us[tid] = ((const float4*)g_U)[tid];
    }
    __syncthreads();

    int px = blockIdx.x * 16 + threadIdx.x;
    int py = blockIdx.y * 8 + threadIdx.y;
    if (px >= 255 || py >= 255) return;

    float cc[9], ss[9];
    int y0 = 2 * py, x0 = 2 * px;
    #pragma unroll
    for (int d = 0; d < 9; d++) {
        int dy = d / 3, dx = d % 3;
        float v = 0.5f * img[(y0 + dy) * 512 + (x0 + dx)];
        __sincosf(v, &ss[d], &cc[d]);
    }

    float r[4][16];
    #pragma unroll
    for (int p = 0; p < 4; p++) {
        int dy = p >> 1, dx = p & 1;
        int ia = dy * 3 + dx, ib = ia + 1, ic = ia + 3, id = ia + 4;
        float c0 = cc[ia], s0 = ss[ia], c1 = cc[ib], s1 = ss[ib];
        float c2 = cc[ic], s2 = ss[ic], c3 = cc[id], s3 = ss[id];
        float hi[4] = { c0 * c1, c0 * s1, s0 * c1, s0 * s1 };
        float lo[4] = { c2 * c3, c2 * s3, s2 * c3, s2 * s3 };
        #pragma unroll
        for (int a = 0; a < 4; a++)
            #pragma unroll
            for (int b = 0; b < 4; b++)
                r[p][a * 4 + b] = hi[a] * lo[b];
    }

    float ez[4][4];
    #pragma unroll
    for (int p = 0; p < 4; p++)
        #pragma unroll
        for (int w = 0; w < 4; w++) ez[p][w] = 0.f;

    #pragma unroll
    for (int k = 0; k < 16; k++) {
        float4 u0 = Us[k * 4 + 0], u1 = Us[k * 4 + 1];
        float4 u2 = Us[k * 4 + 2], u3 = Us[k * 4 + 3];
        float4 v0 = Us[64 + k * 4 + 0], v1 = Us[64 + k * 4 + 1];
        float4 v2 = Us[64 + k * 4 + 2], v3 = Us[64 + k * 4 + 3];
        #pragma unroll
        for (int p = 0; p < 4; p++) {
            float sr = u0.x * r[p][0]  + u0.y * r[p][1]  + u0.z * r[p][2]  + u0.w * r[p][3]
                     + u1.x * r[p][4]  + u1.y * r[p][5]  + u1.z * r[p][6]  + u1.w * r[p][7]
                     + u2.x * r[p][8]  + u2.y * r[p][9]  + u2.z * r[p][10] + u2.w * r[p][11]
                     + u3.x * r[p][12] + u3.y * r[p][13] + u3.z * r[p][14] + u3.w * r[p][15];
            float si = v0.x * r[p][0]  + v0.y * r[p][1]  + v0.z * r[p][2]  + v0.w * r[p][3]
                     + v1.x * r[p][4]  + v1.y * r[p][5]  + v1.z * r[p][6]  + v1.w * r[p][7]
                     + v2.x * r[p][8]  + v2.y * r[p][9]  + v2.z * r[p][10] + v2.w * r[p][11]
                     + v3.x * r[p][12] + v3.y * r[p][13] + v3.z * r[p][14] + v3.w * r[p][15];
            float pk = sr * sr + si * si;
            ez[p][0] += (k & 8) ? -pk : pk;
            ez[p][1] += (k & 4) ? -pk : pk;
            ez[p][2] += (k & 2) ? -pk : pk;
            ez[p][3] += (k & 1) ? -pk : pk;
        }
    }

    #pragma unroll
    for (int w = 0; w < 4; w++) {
        float m = fmaxf(fmaxf(ez[0][w], ez[1][w]), fmaxf(ez[2][w], ez[3][w]));
        g_h1[w * H1_PLANE + py * H1_STRIDE + px] = 1.f / (1.f + __expf(-m));
    }
}

// ---------------------------------------------------------------------------
// k_conv2: 5x5 conv (4->20) + relu + pool2 -> g_h2.
// Thread: 2 pooled px (horiz) x 2 co. Block (16,8) covers 32x8 pooled px.
// Grid (4,16,10) = 640 blocks.
// ---------------------------------------------------------------------------
__global__ void __launch_bounds__(128) k_conv2(const float* __restrict__ w2,
                                               const float* __restrict__ b2) {
    int cog = blockIdx.z;                      // co = cog*2, cog*2+1
    __shared__ float ws[2][100];
    __shared__ __align__(16) float tile[4][20][68];
    int tx = threadIdx.x, ty = threadIdx.y;
    int tid = ty * 16 + tx;

    for (int q = tid; q < 200; q += 128) {
        int co = q / 100, rr = q % 100;
        ws[co][rr] = w2[(cog * 2 + co) * 100 + rr];
    }

    int ix0 = blockIdx.x * 64, iy0 = blockIdx.y * 16;   // pre-pool origin
    // fill: 4 ci x 20 rows x 17 float4
    for (int q = tid; q < 4 * 20 * 17; q += 128) {
        int ci = q / 340, rem = q % 340, ry = rem / 17, f4 = rem % 17;
        int gy = iy0 + ry, gx = ix0 + f4 * 4;
        float4 v = make_float4(0.f, 0.f, 0.f, 0.f);
        if (gy < 255) {
            const float* src = &g_h1[ci * H1_PLANE + gy * H1_STRIDE + gx];
            if (gx + 3 < 255) {
                v = *(const float4*)src;
            } else {
                if (gx + 0 < 255) v.x = src[0];
                if (gx + 1 < 255) v.y = src[1];
                if (gx + 2 < 255) v.z = src[2];
                if (gx + 3 < 255) v.w = src[3];
            }
        }
        *(float4*)&tile[ci][ry][f4 * 4] = v;
    }
    __syncthreads();

    // acc[co][pp][quadrant]
    float acc[2][2][4];
    #pragma unroll
    for (int co = 0; co < 2; co++)
        #pragma unroll
        for (int pp = 0; pp < 2; pp++)
            #pragma unroll
            for (int q = 0; q < 4; q++) acc[co][pp][q] = 0.f;

    int ly = 2 * ty, lx = 4 * tx;              // local pre-pool origin
    #pragma unroll
    for (int ci = 0; ci < 4; ci++) {
        float patch[6][8];
        #pragma unroll
        for (int rr = 0; rr < 6; rr++) {
            const float2* rp = (const float2*)&tile[ci][ly + rr][lx];
            float2 v0 = rp[0], v1 = rp[1], v2 = rp[2], v3 = rp[3];
            patch[rr][0] = v0.x; patch[rr][1] = v0.y;
            patch[rr][2] = v1.x; patch[rr][3] = v1.y;
            patch[rr][4] = v2.x; patch[rr][5] = v2.y;
            patch[rr][6] = v3.x; patch[rr][7] = v3.y;
        }
        #pragma unroll
        for (int co = 0; co < 2; co++) {
            #pragma unroll
            for (int ky = 0; ky < 5; ky++) {
                #pragma unroll
                for (int kx = 0; kx < 5; kx++) {
                    float wv = ws[co][ci * 25 + ky * 5 + kx];
                    #pragma unroll
                    for (int pp = 0; pp < 2; pp++) {
                        int c = 2 * pp + kx;
                        acc[co][pp][0] += wv * patch[ky][c];
                        acc[co][pp][1] += wv * patch[ky][c + 1];
                        acc[co][pp][2] += wv * patch[ky + 1][c];
                        acc[co][pp][3] += wv * patch[ky + 1][c + 1];
                    }
                }
            }
        }
    }

    int py = blockIdx.y * 8 + ty;
    #pragma unroll
    for (int co = 0; co < 2; co++) {
        float bb = b2[cog * 2 + co];
        #pragma unroll
        for (int pp = 0; pp < 2; pp++) {
            int px = blockIdx.x * 32 + 2 * tx + pp;
            if (px >= 125 || py >= 125) continue;
            float m = fmaxf(fmaxf(acc[co][pp][0], acc[co][pp][1]),
                            fmaxf(acc[co][pp][2], acc[co][pp][3]));
            m = fmaxf(m + bb, 0.f);
            g_h2[(cog * 2 + co) * H2_PLANE + py * H2_STRIDE + px] = m;
        }
    }
}

// ---------------------------------------------------------------------------
// k_conv3: 3x3 conv (20->40) + relu + adaptive-max.
// Thread: 4 horiz px x 2 co. Block (16,8) covers 64x8 px. Grid (2,16,20).
// Bins over 123: bin b = [floor(b*123/4), ceil((b+1)*123/4)); overlap rows
// 30,61,92 also belong to the NEXT bin.
// ---------------------------------------------------------------------------
__global__ void __launch_bounds__(128) k_conv3(const float* __restrict__ w3,
                                               const float* __restrict__ b3) {
    int cog = blockIdx.z;                      // co = cog*2, cog*2+1
    __shared__ float ws[2][180];
    __shared__ __align__(16) float tile[5][10][68];
    __shared__ int sbins[2][16];
    int tx = threadIdx.x, ty = threadIdx.y;
    int tid = ty * 16 + tx;

    for (int q = tid; q < 360; q += 128) {
        int co = q / 180, rr = q % 180;
        ws[co][rr] = w3[(cog * 2 + co) * 180 + rr];
    }
    if (tid < 32) ((int*)sbins)[tid] = 0;

    int px0 = blockIdx.x * 64, py0 = blockIdx.y * 8;

    // acc[co][4 px]
    float acc[2][4];
    #pragma unroll
    for (int co = 0; co < 2; co++)
        #pragma unroll
        for (int p = 0; p < 4; p++) acc[co][p] = 0.f;

    int lx = 4 * tx;
    for (int c4 = 0; c4 < 4; c4++) {
        __syncthreads();
        // fill 5 ci x 10 rows x 17 float4
        for (int q = tid; q < 5 * 10 * 17; q += 128) {
            int cil = q / 170, rem = q % 170, ry = rem / 17, f4 = rem % 17;
            int gy = py0 + ry, gx = px0 + f4 * 4;
            float4 v = make_float4(0.f, 0.f, 0.f, 0.f);
            if (gy < 125) {
                const float* src = &g_h2[(c4 * 5 + cil) * H2_PLANE + gy * H2_STRIDE + gx];
                if (gx + 3 < 125) {
                    v = *(const float4*)src;
                } else {
                    if (gx + 0 < 125) v.x = src[0];
                    if (gx + 1 < 125) v.y = src[1];
                    if (gx + 2 < 125) v.z = src[2];
                    if (gx + 3 < 125) v.w = src[3];
                }
            }
            *(float4*)&tile[cil][ry][f4 * 4] = v;
        }
        __syncthreads();

        #pragma unroll
        for (int cil = 0; cil < 5; cil++) {
            int ci = c4 * 5 + cil;
            float patch[3][6];
            #pragma unroll
            for (int rr = 0; rr < 3; rr++) {
                const float2* rp = (const float2*)&tile[cil][ty + rr][lx];
                float2 v0 = rp[0], v1 = rp[1], v2 = rp[2];
                patch[rr][0] = v0.x; patch[rr][1] = v0.y;
                patch[rr][2] = v1.x; patch[rr][3] = v1.y;
                patch[rr][4] = v2.x; patch[rr][5] = v2.y;
            }
            #pragma unroll
            for (int co = 0; co < 2; co++) {
                #pragma unroll
                for (int ky = 0; ky < 3; ky++) {
                    #pragma unroll
                    for (int kx = 0; kx < 3; kx++) {
                        float wv = ws[co][ci * 9 + ky * 3 + kx];
                        acc[co][0] += wv * patch[ky][kx];
                        acc[co][1] += wv * patch[ky][kx + 1];
                        acc[co][2] += wv * patch[ky][kx + 2];
                        acc[co][3] += wv * patch[ky][kx + 3];
                    }
                }
            }
        }
    }

    int gy = py0 + ty;
    if (gy < 123) {
        int bi = (gy * 4) / 123; if (bi > 3) bi = 3;
        bool oy = (bi < 3) && (gy >= (((bi + 1) * 123) >> 2));
        #pragma unroll
        for (int co = 0; co < 2; co++) {
            float bb = b3[cog * 2 + co];
            #pragma unroll
            for (int dx = 0; dx < 4; dx++) {
                int gx = px0 + lx + dx;
                if (gx >= 123) continue;
                float v = fmaxf(acc[co][dx] + bb, 0.f);
                int iv = __float_as_int(v);
                int bj = (gx * 4) / 123; if (bj > 3) bj = 3;
                bool ox = (bj < 3) && (gx >= (((bj + 1) * 123) >> 2));
                atomicMax(&sbins[co][bi * 4 + bj], iv);
                if (oy) atomicMax(&sbins[co][(bi + 1) * 4 + bj], iv);
                if (ox) atomicMax(&sbins[co][bi * 4 + (bj + 1)], iv);
                if (oy && ox) atomicMax(&sbins[co][(bi + 1) * 4 + (bj + 1)], iv);
            }
        }
    }
    __syncthreads();
    if (tid < 32) {
        int co = tid >> 4, b = tid & 15;
        atomicMax((int*)&g_bins[(cog * 2 + co) * 16 + b], sbins[co][b]);
    }
}

// ---------------------------------------------------------------------------
// k_fc: 640 -> 64 (relu) -> 10. One block, 256 threads (8 warps).
// ---------------------------------------------------------------------------
__global__ void __launch_bounds__(256) k_fc(const float* __restrict__ w1,
                                            const float* __restrict__ b1,
                                            const float* __restrict__ w2,
                                            const float* __restrict__ b2,
                                            float* __restrict__ out) {
    __shared__ float h[640];
    __shared__ float f1[64];
    int t = threadIdx.x;
    for (int i = t; i < 640; i += 256) h[i] = g_bins[i];
    __syncthreads();

    int warp = t >> 5, lane = t & 31;
    #pragma unroll
    for (int k = 0; k < 8; k++) {
        int n = warp * 8 + k;
        float s = 0.f;
        for (int j = lane; j < 640; j += 32) s += w1[n * 640 + j] * h[j];
        s += __shfl_xor_sync(0xffffffffu, s, 16);
        s += __shfl_xor_sync(0xffffffffu, s, 8);
        s += __shfl_xor_sync(0xffffffffu, s, 4);
        s += __shfl_xor_sync(0xffffffffu, s, 2);
        s += __shfl_xor_sync(0xffffffffu, s, 1);
        if (lane == 0) f1[n] = fmaxf(s + b1[n], 0.f);
    }
    __syncthreads();
    if (t < 10) {
        float a = b2[t];
        #pragma unroll
        for (int j = 0; j < 64; j++) a += w2[t * 64 + j] * f1[j];
        out[t] = a;
    }
}

// ---------------------------------------------------------------------------
extern "C" void kernel_launch(void* const* d_in, const int* in_sizes, int n_in,
                              void* d_out, int out_size) {
    const float* x   = (const float*)d_in[0];
    const float* qw  = (const float*)d_in[1];
    const float* c2w = (const float*)d_in[2];
    const float* c2b = (const float*)d_in[3];
    const float* c3w = (const float*)d_in[4];
    const float* c3b = (const float*)d_in[5];
    const float* f1w = (const float*)d_in[6];
    const float* f1b = (const float*)d_in[7];
    const float* f2w = (const float*)d_in[8];
    const float* f2b = (const float*)d_in[9];

    k_prep<<<1, 256>>>(qw);

    dim3 bq(16, 8), gq(16, 32);
    k_qconv<<<gq, bq>>>(x);

    dim3 bc(16, 8);
    dim3 g2(4, 16, 10);
    k_conv2<<<g2, bc>>>(c2w, c2b);

    dim3 g3(2, 16, 20);
    k_conv3<<<g3, bc>>>(c3w, c3b);

    k_fc<<<1, 256>>>(f1w, f1b, f2w, f2b, (float*)d_out);
}